// round 3
// baseline (speedup 1.0000x reference)
#include <cuda_runtime.h>

#define BB 4
#define CC 192
#define HH 256
#define WWID 256
#define WS 12
#define NWH 22                    // 264/12 windows per side
#define NWIN (BB*NWH*NWH)         // 1936
#define NTOK 144                  // 12*12
#define HEADS 6
#define DH 32
#define QKV3 576
#define KP 96                     // 192/2 k-pairs
#define XSTR 194                  // even padded token-row stride (floats)

// Scratch (static device globals; no runtime allocation)
__device__ float  g_qkv[(size_t)NWIN * NTOK * QKV3];  // [win][n][576] : q|k|v
__device__ float  g_o[(size_t)NWIN * NTOK * CC];      // [win][n][192]
__device__ float2 g_w2q[QKV3 * KP];                   // [(chunk*96+kp)*64+o] k-pair packed
__device__ float2 g_w2p[CC * KP];

#define SMEM_GEMM ((NTOK*XSTR + KP*64*2) * 4)         // 160,896 B
#define SMEM_ATTN (2 * NTOK * DH * 4)                 // 36,864 B

// ---- packed f32x2 FMA (sm_103a FFMA2; only reachable via PTX) --------------
__device__ __forceinline__ unsigned long long f32x2_fma(
    unsigned long long a, unsigned long long b, unsigned long long c) {
    unsigned long long d;
    asm("fma.rn.f32x2 %0, %1, %2, %3;" : "=l"(d) : "l"(a), "l"(b), "l"(c));
    return d;
}
__device__ __forceinline__ float f32x2_hsum(unsigned long long u) {
    float lo, hi;
    asm("mov.b64 {%0, %1}, %2;" : "=f"(lo), "=f"(hi) : "l"(u));
    return lo + hi;
}

// ---------------------------------------------------------------------------
// Kernel 0: one-shot weight repack into k-pair-major layout:
//   w2[(chunk*KP + kp)*64 + o] = { w[(chunk*64+o)*192 + 2kp], ... + 2kp+1 }
// Coalesced writes; reads are L2-resident (weights total 589KB).
// ---------------------------------------------------------------------------
__global__ void k_wprep(const float* __restrict__ wqkv,
                        const float* __restrict__ wproj) {
    const int t = blockIdx.x * 256 + threadIdx.x;
    if (t < QKV3 * KP) {
        const int o = t & 63, rest = t >> 6;
        const int kp = rest % KP, chunk = rest / KP;
        const int og = chunk * 64 + o;
        g_w2q[t] = make_float2(wqkv[(size_t)og * CC + 2 * kp],
                               wqkv[(size_t)og * CC + 2 * kp + 1]);
    }
    if (t < CC * KP) {
        const int o = t & 63, rest = t >> 6;
        const int kp = rest % KP, chunk = rest / KP;
        const int og = chunk * 64 + o;
        g_w2p[t] = make_float2(wproj[(size_t)og * CC + 2 * kp],
                               wproj[(size_t)og * CC + 2 * kp + 1]);
    }
}

// ---------------------------------------------------------------------------
// Kernel 1: per-window QKV GEMM. qkv[n,o] = sum_c xw[n,c]*wqkv[o,c]
// CTA = window; 16x16 threads; tokens n = ty+16r (r<9); outputs o = tx+16*oc.
// f32x2 lanes carry (k even, k odd) partial sums -> zero broadcast MOVs.
// ---------------------------------------------------------------------------
__global__ __launch_bounds__(256) void k_qkv(const float* __restrict__ x) {
    const int win = blockIdx.x;
    const int b   = win / (NWH * NWH);
    const int rem = win % (NWH * NWH);
    const int wh  = rem / NWH, wwi = rem % NWH;

    extern __shared__ float sm[];
    float* xs = sm;                                  // [144][194]
    float* ws = sm + NTOK * XSTR;                    // [96][64] float2 = 49KB

    const int tx = threadIdx.x, ty = threadIdx.y;
    const int tid = ty * 16 + tx;

    // Gather window (reflect pad)
    for (int e = tid; e < NTOK * CC; e += 256) {
        int c = e / NTOK, n = e % NTOK;
        int i = n / WS, j = n % WS;
        int h = wh * WS + i;  if (h >= HH)   h = 2 * HH   - 2 - h;
        int w = wwi * WS + j; if (w >= WWID) w = 2 * WWID - 2 - w;
        xs[n * XSTR + c] = x[(((size_t)b * CC + c) * HH + h) * WWID + w];
    }

    float* outp = g_qkv + (size_t)win * NTOK * QKV3;

    for (int chunk = 0; chunk < 9; ++chunk) {        // 9 x 64 output cols
        __syncthreads();
        {   // coalesced float4 copy of prepacked chunk (96*64 float2)
            const float4* src = (const float4*)(g_w2q + (size_t)chunk * KP * 64);
            float4* dst = (float4*)ws;
            for (int e = tid; e < KP * 64 / 2; e += 256) dst[e] = src[e];
        }
        __syncthreads();

        unsigned long long acc[9][4];
        #pragma unroll
        for (int r = 0; r < 9; ++r)
            #pragma unroll
            for (int oc = 0; oc < 4; ++oc) acc[r][oc] = 0ull;

        #pragma unroll 4
        for (int kp = 0; kp < KP; ++kp) {
            unsigned long long wv[4];
            #pragma unroll
            for (int oc = 0; oc < 4; ++oc)
                wv[oc] = *(const unsigned long long*)&ws[(kp * 64 + tx + 16 * oc) * 2];
            #pragma unroll
            for (int r = 0; r < 9; ++r) {
                const unsigned long long ap =
                    *(const unsigned long long*)&xs[(ty + 16 * r) * XSTR + 2 * kp];
                #pragma unroll
                for (int oc = 0; oc < 4; ++oc)
                    acc[r][oc] = f32x2_fma(ap, wv[oc], acc[r][oc]);
            }
        }

        #pragma unroll
        for (int r = 0; r < 9; ++r) {
            float* op = outp + (size_t)(ty + 16 * r) * QKV3 + chunk * 64;
            #pragma unroll
            for (int oc = 0; oc < 4; ++oc)
                op[oc * 16 + tx] = f32x2_hsum(acc[r][oc]);
        }
    }
}

// ---------------------------------------------------------------------------
// Kernel 2: masked dilated attention. Only 15 valid keys per query
// (i2==i1 mod 3, j2==j1 mod 3, self excluded) -> 16 register dots.
// CTA = (window, head); 160 threads, one row per thread (144 active).
// ---------------------------------------------------------------------------
__global__ __launch_bounds__(160) void k_attn() {
    const int win  = blockIdx.x / HEADS;
    const int head = blockIdx.x % HEADS;

    extern __shared__ float sm[];
    float* ks = sm;                 // [144][32]
    float* vs = sm + NTOK * DH;     // [144][32]

    const int tid = threadIdx.x;
    const float* base = g_qkv + (size_t)win * NTOK * QKV3;

    for (int e4 = tid; e4 < NTOK * 8; e4 += 160) {
        int row = e4 >> 3, d4 = e4 & 7;
        *(float4*)(ks + row * DH + d4 * 4) =
            *(const float4*)(base + (size_t)row * QKV3 + CC + head * DH + d4 * 4);
        *(float4*)(vs + row * DH + d4 * 4) =
            *(const float4*)(base + (size_t)row * QKV3 + 2 * CC + head * DH + d4 * 4);
    }
    __syncthreads();

    if (tid < NTOK) {
        const int r = tid, i1 = r / WS, j1 = r % WS;
        const float scale = 0.17677669529663687f;   // 32^-0.5

        float4 q[8];
        const float4* qp = (const float4*)(base + (size_t)r * QKV3 + head * DH);
        #pragma unroll
        for (int d = 0; d < 8; ++d) {
            q[d] = qp[d];
            q[d].x *= scale; q[d].y *= scale; q[d].z *= scale; q[d].w *= scale;
        }

        float s[16]; int ms[16];
        float mx = -1e30f;
        const int ib = i1 % 3, jb = j1 % 3;
        #pragma unroll
        for (int ii = 0; ii < 4; ++ii) {
            #pragma unroll
            for (int jj = 0; jj < 4; ++jj) {
                const int idx = ii * 4 + jj;
                const int m = (ib + 3 * ii) * WS + (jb + 3 * jj);
                ms[idx] = m;
                if (m == r) { s[idx] = -1e30f; continue; }   // self masked
                const float4* kp = (const float4*)(ks + m * DH);
                float a0 = 0.f, a1 = 0.f, a2 = 0.f, a3 = 0.f;
                #pragma unroll
                for (int d = 0; d < 8; ++d) {
                    float4 kv = kp[d];
                    a0 += q[d].x * kv.x; a1 += q[d].y * kv.y;
                    a2 += q[d].z * kv.z; a3 += q[d].w * kv.w;
                }
                float sv = (a0 + a1) + (a2 + a3);
                s[idx] = sv;
                mx = fmaxf(mx, sv);
            }
        }

        float sum = 0.f;
        #pragma unroll
        for (int idx = 0; idx < 16; ++idx) {
            float p = __expf(s[idx] - mx);   // self: exp(-huge) -> 0
            s[idx] = p; sum += p;
        }
        const float inv = 1.0f / sum;

        float o[DH];
        #pragma unroll
        for (int d = 0; d < DH; ++d) o[d] = 0.f;
        #pragma unroll
        for (int idx = 0; idx < 16; ++idx) {
            const float p = s[idx] * inv;
            const float* vp = vs + ms[idx] * DH;
            #pragma unroll
            for (int d = 0; d < DH; ++d) o[d] += p * vp[d];
        }

        float* op = g_o + (size_t)win * NTOK * CC + (size_t)r * CC + head * DH;
        #pragma unroll
        for (int d4 = 0; d4 < 8; ++d4)
            *(float4*)(op + d4 * 4) =
                make_float4(o[d4*4], o[d4*4+1], o[d4*4+2], o[d4*4+3]);
    }
}

// ---------------------------------------------------------------------------
// Kernel 3: per-window proj GEMM + scatter (crop pad), same f32x2-k scheme.
// Tokens n = tx+16r so the global scatter stores coalesce along w.
// ---------------------------------------------------------------------------
__global__ __launch_bounds__(256) void k_proj(float* __restrict__ out) {
    const int win = blockIdx.x;
    const int b   = win / (NWH * NWH);
    const int rem = win % (NWH * NWH);
    const int wh  = rem / NWH, wwi = rem % NWH;

    extern __shared__ float sm[];
    float* os = sm;                                  // [144][194]
    float* ws = sm + NTOK * XSTR;                    // [96][64] float2

    const int tx = threadIdx.x, ty = threadIdx.y;
    const int tid = ty * 16 + tx;

    const float* inp = g_o + (size_t)win * NTOK * CC;
    for (int e = tid; e < NTOK * CC; e += 256) {
        int n = e / CC, c = e % CC;
        os[n * XSTR + c] = inp[e];
    }

    for (int chunk = 0; chunk < 3; ++chunk) {        // 3 x 64 output channels
        __syncthreads();
        {
            const float4* src = (const float4*)(g_w2p + (size_t)chunk * KP * 64);
            float4* dst = (float4*)ws;
            for (int e = tid; e < KP * 64 / 2; e += 256) dst[e] = src[e];
        }
        __syncthreads();

        unsigned long long acc[9][4];
        #pragma unroll
        for (int r = 0; r < 9; ++r)
            #pragma unroll
            for (int oc = 0; oc < 4; ++oc) acc[r][oc] = 0ull;

        #pragma unroll 4
        for (int kp = 0; kp < KP; ++kp) {
            unsigned long long wv[4];
            #pragma unroll
            for (int oc = 0; oc < 4; ++oc)
                wv[oc] = *(const unsigned long long*)&ws[(kp * 64 + ty + 16 * oc) * 2];
            #pragma unroll
            for (int r = 0; r < 9; ++r) {
                const unsigned long long ap =
                    *(const unsigned long long*)&os[(tx + 16 * r) * XSTR + 2 * kp];
                #pragma unroll
                for (int oc = 0; oc < 4; ++oc)
                    acc[r][oc] = f32x2_fma(ap, wv[oc], acc[r][oc]);
            }
        }

        #pragma unroll
        for (int r = 0; r < 9; ++r) {
            const int n = tx + 16 * r;
            const int h = wh * WS + n / WS;
            const int w = wwi * WS + n % WS;
            if (h < HH && w < WWID) {
                #pragma unroll
                for (int oc = 0; oc < 4; ++oc) {
                    const int ocg = chunk * 64 + ty + 16 * oc;
                    out[(((size_t)b * CC + ocg) * HH + h) * WWID + w] =
                        f32x2_hsum(acc[r][oc]);
                }
            }
        }
    }
}

// ---------------------------------------------------------------------------
extern "C" void kernel_launch(void* const* d_in, const int* in_sizes, int n_in,
                              void* d_out, int out_size) {
    const float* x     = (const float*)d_in[0];
    const float* wqkv  = (const float*)d_in[1];
    const float* wproj = (const float*)d_in[2];
    float* out = (float*)d_out;

    cudaFuncSetAttribute(k_qkv,  cudaFuncAttributeMaxDynamicSharedMemorySize, SMEM_GEMM);
    cudaFuncSetAttribute(k_attn, cudaFuncAttributeMaxDynamicSharedMemorySize, SMEM_ATTN);
    cudaFuncSetAttribute(k_proj, cudaFuncAttributeMaxDynamicSharedMemorySize, SMEM_GEMM);

    k_wprep<<<(QKV3 * KP + 255) / 256, 256>>>(wqkv, wproj);
    k_qkv  <<<NWIN, dim3(16, 16), SMEM_GEMM>>>(x);
    k_attn <<<NWIN * HEADS, 160,  SMEM_ATTN>>>();
    k_proj <<<NWIN, dim3(16, 16), SMEM_GEMM>>>(out);
}

// round 12
// speedup vs baseline: 2.0619x; 2.0619x over previous
#include <cuda_runtime.h>
#include <cuda_bf16.h>
#include <cstdint>

#define BB 4
#define CC 192
#define HH 256
#define WWID 256
#define WS 12
#define NWH 22
#define NWIN (BB*NWH*NWH)       // 1936
#define NTOK 144
#define HEADS 6
#define DH 32
#define QKV3 576
#define TOTTOK (NWIN*NTOK)      // 278784 = 128 * 2178 exactly
#define MT 128
#define NTILE (TOTTOK/MT)       // 2178
#define NCH_Q 9
#define NCH_P 3
#define STRB 400                // smem row stride bytes (200 bf16; conflict-free for ldmatrix)

// ---- device scratch (no runtime allocation) -------------------------------
__device__ float g_qkv[(size_t)TOTTOK * QKV3];   // fp32 q|k|v per token
__device__ uint4 g_aoh[(size_t)TOTTOK * 24];     // attn out hi  [token][192] bf16
__device__ uint4 g_aol[(size_t)TOTTOK * 24];     // attn out lo
__device__ uint4 g_wqh[QKV3 * 24];               // wqkv hi  [o][192] bf16
__device__ uint4 g_wql[QKV3 * 24];
__device__ uint4 g_wph[CC * 24];                 // wproj hi
__device__ uint4 g_wpl[CC * 24];

// ---- smem layout for GEMM kernels (bytes) ---------------------------------
#define SM_AHI 0                 // 128*400 = 51200
#define SM_ALO 51200
#define SM_BHI 102400            // 64*400 = 25600
#define SM_BLO 128000
#define SM_STAGE 153600          // 128*65*4 = 33280
#define SMEM_MMA 186880
#define SMEM_ATTN (2 * NTOK * DH * 4)

// ---- PTX helpers (plain sm_80-era ISA only; no tcgen05 on this target) ----
__device__ __forceinline__ uint32_t smem_u32(const void* p) {
    uint32_t a;
    asm("{ .reg .u64 t; cvta.to.shared.u64 t, %1; cvt.u32.u64 %0, t; }" : "=r"(a) : "l"(p));
    return a;
}
#define LDSM4(r, addr) \
    asm volatile("ldmatrix.sync.aligned.m8n8.x4.shared.b16 {%0,%1,%2,%3}, [%4];" \
        : "=r"((r)[0]), "=r"((r)[1]), "=r"((r)[2]), "=r"((r)[3]) : "r"(addr))
#define LDSM2(r, addr) \
    asm volatile("ldmatrix.sync.aligned.m8n8.x2.shared.b16 {%0,%1}, [%2];" \
        : "=r"((r)[0]), "=r"((r)[1]) : "r"(addr))
#define MMA(d, a, b) \
    asm volatile("mma.sync.aligned.m16n8k16.row.col.f32.bf16.bf16.f32 " \
        "{%0,%1,%2,%3}, {%4,%5,%6,%7}, {%8,%9}, {%0,%1,%2,%3};" \
        : "+f"((d)[0]), "+f"((d)[1]), "+f"((d)[2]), "+f"((d)[3]) \
        : "r"((a)[0]), "r"((a)[1]), "r"((a)[2]), "r"((a)[3]), "r"((b)[0]), "r"((b)[1]))

union BF8 { __nv_bfloat16 h[8]; uint4 u; };

__device__ __forceinline__ void split8(const float* v, BF8& Uh, BF8& Ul) {
    #pragma unroll
    for (int c = 0; c < 8; ++c) {
        __nv_bfloat16 hb = __float2bfloat16(v[c]);
        Uh.h[c] = hb;
        Ul.h[c] = __float2bfloat16(v[c] - __bfloat162float(hb));
    }
}

// ---------------------------------------------------------------------------
// Weight prep: split fp32 -> bf16 hi/lo, plain [o][192] rows.
// ---------------------------------------------------------------------------
__global__ void k_prep_w(const float* __restrict__ wqkv,
                         const float* __restrict__ wproj) {
    int t = blockIdx.x * 256 + threadIdx.x;
    const float* src;
    uint4 *dhi, *dlo;
    if (t < QKV3 * 24) { src = wqkv; dhi = g_wqh; dlo = g_wql; }
    else {
        t -= QKV3 * 24;
        if (t >= CC * 24) return;
        src = wproj; dhi = g_wph; dlo = g_wpl;
    }
    const int o = t / 24, k0 = (t % 24) * 8;
    float v[8];
    #pragma unroll
    for (int c = 0; c < 8; ++c) v[c] = src[(size_t)o * CC + k0 + c];
    BF8 Uh, Ul; split8(v, Uh, Ul);
    dhi[t] = Uh.u; dlo[t] = Ul.u;
}

// ---------------------------------------------------------------------------
// GEMM core (shared by QKV and proj): warp 4x2 grid, warp tile 32x32,
// m16n8k16 bf16 mma with bf16x3 split, fp32 accumulate.
// ---------------------------------------------------------------------------
__device__ __forceinline__ void gemm_chunk(uint32_t sb, int lane, int mb, int nb,
                                           float c[2][4][4]) {
    const uint32_t a_off = (uint32_t)((lane & 7) + ((lane >> 3) & 1) * 8) * STRB
                         + (uint32_t)(lane >> 4) * 16;
    const uint32_t b_off = (uint32_t)(lane & 7) * STRB + (uint32_t)((lane >> 3) & 1) * 16;

    #pragma unroll
    for (int mf = 0; mf < 2; ++mf)
        #pragma unroll
        for (int t = 0; t < 4; ++t)
            #pragma unroll
            for (int i = 0; i < 4; ++i) c[mf][t][i] = 0.f;

    #pragma unroll
    for (int s = 0; s < 12; ++s) {
        const uint32_t k0b = (uint32_t)s * 32;      // 16 bf16 per step
        uint32_t ah0[4], ah1[4], al0[4], al1[4];
        const uint32_t ahA = sb + SM_AHI + (uint32_t)mb * STRB + a_off + k0b;
        const uint32_t alA = sb + SM_ALO + (uint32_t)mb * STRB + a_off + k0b;
        LDSM4(ah0, ahA);
        LDSM4(ah1, ahA + 16 * STRB);
        LDSM4(al0, alA);
        LDSM4(al1, alA + 16 * STRB);

        uint32_t bh[4][2], bl[4][2];
        #pragma unroll
        for (int t = 0; t < 4; ++t) {
            const uint32_t bA = sb + SM_BHI + (uint32_t)(nb + t * 8) * STRB + b_off + k0b;
            LDSM2(bh[t], bA);
            LDSM2(bl[t], bA + (SM_BLO - SM_BHI));
        }
        #pragma unroll
        for (int t = 0; t < 4; ++t) { MMA(c[0][t], ah0, bh[t]); MMA(c[1][t], ah1, bh[t]); }
        #pragma unroll
        for (int t = 0; t < 4; ++t) { MMA(c[0][t], ah0, bl[t]); MMA(c[1][t], ah1, bl[t]); }
        #pragma unroll
        for (int t = 0; t < 4; ++t) { MMA(c[0][t], al0, bh[t]); MMA(c[1][t], al1, bh[t]); }
    }
}

__device__ __forceinline__ void store_frags(float* stage, int lane, int mb, int nb,
                                            float c[2][4][4]) {
    const int r0 = mb + (lane >> 2), cb = nb + (lane & 3) * 2;
    #pragma unroll
    for (int mf = 0; mf < 2; ++mf) {
        const int rr = r0 + mf * 16;
        #pragma unroll
        for (int t = 0; t < 4; ++t) {
            stage[rr * 65 + cb + t * 8]       = c[mf][t][0];
            stage[rr * 65 + cb + 1 + t * 8]   = c[mf][t][1];
            stage[(rr + 8) * 65 + cb + t * 8]     = c[mf][t][2];
            stage[(rr + 8) * 65 + cb + 1 + t * 8] = c[mf][t][3];
        }
    }
}

// ---------------------------------------------------------------------------
// QKV GEMM: CTA = 128-token tile. Fused reflect-pad gather -> bf16 hi/lo
// smem A; 9 chunks of 64 output cols; HMMA bf16x3 core.
// ---------------------------------------------------------------------------
__global__ __launch_bounds__(256) void k_qkv_mma(const float* __restrict__ x) {
    extern __shared__ char smem[];
    const uint32_t sb = smem_u32(smem);
    const int tid = threadIdx.x, wid = tid / 32, lane = tid & 31;
    const int tile = blockIdx.x;

    // Fused gather (coalesced along tokens for each channel group)
    for (int e = tid; e < MT * 24; e += 256) {
        const int row = e & 127, grp = e >> 7;
        const int token = tile * MT + row;
        const int win = token / NTOK, n = token % NTOK;
        const int b = win / (NWH * NWH), rem = win % (NWH * NWH);
        int h = (rem / NWH) * WS + n / WS;  if (h >= HH)   h = 2 * HH   - 2 - h;
        int w = (rem % NWH) * WS + n % WS;  if (w >= WWID) w = 2 * WWID - 2 - w;
        const int c0 = grp * 8;
        float v[8];
        #pragma unroll
        for (int cc = 0; cc < 8; ++cc)
            v[cc] = x[(((size_t)b * CC + c0 + cc) * HH + h) * WWID + w];
        BF8 Uh, Ul; split8(v, Uh, Ul);
        *(uint4*)(smem + SM_AHI + row * STRB + c0 * 2) = Uh.u;
        *(uint4*)(smem + SM_ALO + row * STRB + c0 * 2) = Ul.u;
    }

    const int mb = (wid >> 1) * 32, nb = (wid & 1) * 32;
    float* stage = (float*)(smem + SM_STAGE);
    float* outbase = g_qkv + (size_t)tile * MT * QKV3;

    for (int chunk = 0; chunk < NCH_Q; ++chunk) {
        __syncthreads();
        for (int e = tid; e < 64 * 24; e += 256) {       // B chunk -> smem
            const int ol = e / 24, part = e % 24;
            *(uint4*)(smem + SM_BHI + ol * STRB + part * 16) = g_wqh[(chunk * 64 + ol) * 24 + part];
            *(uint4*)(smem + SM_BLO + ol * STRB + part * 16) = g_wql[(chunk * 64 + ol) * 24 + part];
        }
        __syncthreads();

        float c[2][4][4];
        gemm_chunk(sb, lane, mb, nb, c);
        store_frags(stage, lane, mb, nb, c);
        __syncthreads();
        for (int e = tid; e < MT * 64; e += 256) {
            const int tok = e >> 6, cc = e & 63;
            outbase[(size_t)tok * QKV3 + chunk * 64 + cc] = stage[tok * 65 + cc];
        }
    }
}

// ---------------------------------------------------------------------------
// Attention, class-sorted (mask is block-diagonal over (i%3, j%3) classes).
// Writes bf16 hi/lo rows [token][192] for the proj GEMM.
// ---------------------------------------------------------------------------
__global__ __launch_bounds__(160) void k_attn() {
    const int win  = blockIdx.x / HEADS;
    const int head = blockIdx.x % HEADS;

    extern __shared__ float sm[];
    float* ks = sm;                 // [144][32], class-sorted rows
    float* vs = sm + NTOK * DH;

    const int tid = threadIdx.x;
    const float* base = g_qkv + (size_t)win * NTOK * QKV3;

    for (int e4 = tid; e4 < NTOK * 8; e4 += 160) {
        const int row = e4 >> 3, d4 = e4 & 7;
        const int i = row / WS, j = row % WS;
        const int p = ((i % 3) * 3 + (j % 3)) * 16 + (i / 3) * 4 + (j / 3);
        *(float4*)(ks + p * DH + d4 * 4) =
            *(const float4*)(base + (size_t)row * QKV3 + CC + head * DH + d4 * 4);
        *(float4*)(vs + p * DH + d4 * 4) =
            *(const float4*)(base + (size_t)row * QKV3 + 2 * CC + head * DH + d4 * 4);
    }
    __syncthreads();

    if (tid < NTOK) {
        const int cls = tid >> 4, qi = tid & 15;
        const int ib = cls / 3, jb = cls % 3;
        const int n = ((qi >> 2) * 3 + ib) * WS + ((qi & 3) * 3 + jb);
        const float scale = 0.17677669529663687f;   // 32^-0.5

        float4 q[8];
        const float4* qp = (const float4*)(base + (size_t)n * QKV3 + head * DH);
        #pragma unroll
        for (int d = 0; d < 8; ++d) {
            q[d] = qp[d];
            q[d].x *= scale; q[d].y *= scale; q[d].z *= scale; q[d].w *= scale;
        }

        const float* kbase = ks + cls * 16 * DH;
        const float* vbase = vs + cls * 16 * DH;

        float s[16];
        float mx = -1e30f;
        #pragma unroll
        for (int m = 0; m < 16; ++m) {
            if (m == qi) { s[m] = -1e30f; continue; }     // self masked
            const float4* kp = (const float4*)(kbase + m * DH);
            float a0 = 0.f, a1 = 0.f, a2 = 0.f, a3 = 0.f;
            #pragma unroll
            for (int d = 0; d < 8; ++d) {
                float4 kv = kp[d];
                a0 += q[d].x * kv.x; a1 += q[d].y * kv.y;
                a2 += q[d].z * kv.z; a3 += q[d].w * kv.w;
            }
            const float sv = (a0 + a1) + (a2 + a3);
            s[m] = sv;
            mx = fmaxf(mx, sv);
        }

        float sum = 0.f;
        #pragma unroll
        for (int m = 0; m < 16; ++m) {
            const float p = __expf(s[m] - mx);            // self -> 0
            s[m] = p; sum += p;
        }
        const float inv = 1.0f / sum;

        float o[DH];
        #pragma unroll
        for (int d = 0; d < DH; ++d) o[d] = 0.f;
        #pragma unroll
        for (int m = 0; m < 16; ++m) {
            const float p = s[m] * inv;
            const float* vp = vbase + m * DH;
            #pragma unroll
            for (int d = 0; d < DH; ++d) o[d] += p * vp[d];
        }

        const int token = win * NTOK + n;
        #pragma unroll
        for (int g = 0; g < 4; ++g) {
            BF8 Uh, Ul; split8(o + g * 8, Uh, Ul);
            g_aoh[(size_t)token * 24 + head * 4 + g] = Uh.u;
            g_aol[(size_t)token * 24 + head * 4 + g] = Ul.u;
        }
    }
}

// ---------------------------------------------------------------------------
// Proj GEMM: A = attn output (bf16 hi/lo from gmem), 3 chunks of 64 channels,
// epilogue scatters (crop pad) to output.
// ---------------------------------------------------------------------------
__global__ __launch_bounds__(256) void k_proj_mma(float* __restrict__ out) {
    extern __shared__ char smem[];
    const uint32_t sb = smem_u32(smem);
    const int tid = threadIdx.x, wid = tid / 32, lane = tid & 31;
    const int tile = blockIdx.x;

    for (int e = tid; e < MT * 24; e += 256) {           // A -> smem (flat coalesced)
        const int row = e / 24, part = e % 24;
        *(uint4*)(smem + SM_AHI + row * STRB + part * 16) = g_aoh[(size_t)tile * MT * 24 + e];
        *(uint4*)(smem + SM_ALO + row * STRB + part * 16) = g_aol[(size_t)tile * MT * 24 + e];
    }

    const int mb = (wid >> 1) * 32, nb = (wid & 1) * 32;
    float* stage = (float*)(smem + SM_STAGE);

    for (int chunk = 0; chunk < NCH_P; ++chunk) {
        __syncthreads();
        for (int e = tid; e < 64 * 24; e += 256) {
            const int ol = e / 24, part = e % 24;
            *(uint4*)(smem + SM_BHI + ol * STRB + part * 16) = g_wph[(chunk * 64 + ol) * 24 + part];
            *(uint4*)(smem + SM_BLO + ol * STRB + part * 16) = g_wpl[(chunk * 64 + ol) * 24 + part];
        }
        __syncthreads();

        float c[2][4][4];
        gemm_chunk(sb, lane, mb, nb, c);
        store_frags(stage, lane, mb, nb, c);
        __syncthreads();

        for (int e = tid; e < 64 * MT; e += 256) {
            const int oc = e >> 7, tok = e & 127;
            const float v = stage[tok * 65 + oc];
            const int token = tile * MT + tok;
            const int win = token / NTOK, n = token % NTOK;
            const int b = win / (NWH * NWH), rem = win % (NWH * NWH);
            const int h = (rem / NWH) * WS + n / WS;
            const int w = (rem % NWH) * WS + n % WS;
            if (h < HH && w < WWID)
                out[(((size_t)b * CC + chunk * 64 + oc) * HH + h) * WWID + w] = v;
        }
    }
}

// ---------------------------------------------------------------------------
extern "C" void kernel_launch(void* const* d_in, const int* in_sizes, int n_in,
                              void* d_out, int out_size) {
    const float* x     = (const float*)d_in[0];
    const float* wqkv  = (const float*)d_in[1];
    const float* wproj = (const float*)d_in[2];
    float* out = (float*)d_out;

    cudaFuncSetAttribute(k_qkv_mma,  cudaFuncAttributeMaxDynamicSharedMemorySize, SMEM_MMA);
    cudaFuncSetAttribute(k_proj_mma, cudaFuncAttributeMaxDynamicSharedMemorySize, SMEM_MMA);
    cudaFuncSetAttribute(k_attn,     cudaFuncAttributeMaxDynamicSharedMemorySize, SMEM_ATTN);

    k_prep_w  <<<72, 256>>>(wqkv, wproj);
    k_qkv_mma <<<NTILE, 256, SMEM_MMA>>>(x);
    k_attn    <<<NWIN * HEADS, 160, SMEM_ATTN>>>();
    k_proj_mma<<<NTILE, 256, SMEM_MMA>>>(out);
}